// round 12
// baseline (speedup 1.0000x reference)
#include <cuda_runtime.h>
#include <math.h>

#define B_  4
#define S_  1024
#define D_  1024
#define H_  16
#define DH_ 64
#define M_  (B_*S_)
#define EPS_ 1e-5f

typedef unsigned long long ull;

// ---------------- scratch (no allocations allowed) ----------------
__device__ __align__(16) float g_h0[M_ * D_];
__device__ __align__(16) float g_mu[D_];
__device__ __align__(16) float g_rstd[D_];

// ---------------- packed f32x2 helpers ----------------------------
__device__ __forceinline__ ull d_fma2(ull a, ull b, ull c) {
    ull d;
    asm("fma.rn.f32x2 %0, %1, %2, %3;" : "=l"(d) : "l"(a), "l"(b), "l"(c));
    return d;
}
__device__ __forceinline__ ull d_add2(ull a, ull b) {
    ull d;
    asm("add.rn.f32x2 %0, %1, %2;" : "=l"(d) : "l"(a), "l"(b));
    return d;
}
__device__ __forceinline__ ull d_mul2(ull a, ull b) {
    ull d;
    asm("mul.rn.f32x2 %0, %1, %2;" : "=l"(d) : "l"(a), "l"(b));
    return d;
}
__device__ __forceinline__ ull pack2(float x, float y) {
    ull d;
    asm("mov.b64 %0, {%1, %2};" : "=l"(d) : "f"(x), "f"(y));
    return d;
}
__device__ __forceinline__ float2 unpack2(ull v) {
    float2 r;
    asm("mov.b64 {%0, %1}, %2;" : "=f"(r.x), "=f"(r.y) : "l"(v));
    return r;
}
__device__ __forceinline__ void cp16(unsigned int sdst, const void* gsrc) {
    asm volatile("cp.async.cg.shared.global [%0], [%1], 16;"
                 :: "r"(sdst), "l"(gsrc));
}

union F4U2 { float4 f; ulonglong2 u; };

// =================================================================
// Kernel 1: h0[m,n] = scale[n] * sum_k x[m,k] * W[n,k]
// =================================================================
#define BM 64
#define BN 64
#define BK 16

__global__ __launch_bounds__(256) void gemm_k(const float* __restrict__ x,
                                              const float* __restrict__ W,
                                              const float* __restrict__ scale)
{
    __shared__ float As[BK][BM];
    __shared__ float Bs[BK][BN];

    const int m0  = blockIdx.y * BM;
    const int n0  = blockIdx.x * BN;
    const int tid = threadIdx.x;
    const int lrow = tid >> 2;
    const int lk   = (tid & 3) << 2;
    const int tx = tid & 15;
    const int ty = tid >> 4;

    float acc[4][4];
#pragma unroll
    for (int i = 0; i < 4; i++)
#pragma unroll
        for (int j = 0; j < 4; j++) acc[i][j] = 0.f;

    const float* xg = x + (size_t)(m0 + lrow) * D_;
    const float* wg = W + (size_t)(n0 + lrow) * D_;

    for (int k0 = 0; k0 < D_; k0 += BK) {
        float4 a = *(const float4*)(xg + k0 + lk);
        float4 b = *(const float4*)(wg + k0 + lk);
        __syncthreads();
        As[lk + 0][lrow] = a.x; As[lk + 1][lrow] = a.y;
        As[lk + 2][lrow] = a.z; As[lk + 3][lrow] = a.w;
        Bs[lk + 0][lrow] = b.x; Bs[lk + 1][lrow] = b.y;
        Bs[lk + 2][lrow] = b.z; Bs[lk + 3][lrow] = b.w;
        __syncthreads();
#pragma unroll
        for (int k = 0; k < BK; k++) {
            float4 av = *(const float4*)&As[k][ty << 2];
            float4 bv = *(const float4*)&Bs[k][tx << 2];
            acc[0][0] += av.x * bv.x; acc[0][1] += av.x * bv.y;
            acc[0][2] += av.x * bv.z; acc[0][3] += av.x * bv.w;
            acc[1][0] += av.y * bv.x; acc[1][1] += av.y * bv.y;
            acc[1][2] += av.y * bv.z; acc[1][3] += av.y * bv.w;
            acc[2][0] += av.z * bv.x; acc[2][1] += av.z * bv.y;
            acc[2][2] += av.z * bv.z; acc[2][3] += av.z * bv.w;
            acc[3][0] += av.w * bv.x; acc[3][1] += av.w * bv.y;
            acc[3][2] += av.w * bv.z; acc[3][3] += av.w * bv.w;
        }
    }

    const int nc = n0 + (tx << 2);
    float4 sc = *(const float4*)(scale + nc);
#pragma unroll
    for (int i = 0; i < 4; i++) {
        const int row = m0 + (ty << 2) + i;
        float4 o;
        o.x = acc[i][0] * sc.x; o.y = acc[i][1] * sc.y;
        o.z = acc[i][2] * sc.z; o.w = acc[i][3] * sc.w;
        *(float4*)&g_h0[(size_t)row * D_ + nc] = o;
    }
}

// =================================================================
// Kernel 2: per-feature mean / rstd
// =================================================================
__global__ __launch_bounds__(256) void stats_k()
{
    const int f = blockIdx.x;
    const int tid = threadIdx.x;
    float s = 0.f, s2 = 0.f;
    for (int r = tid; r < M_; r += 256) {
        float v = g_h0[(size_t)r * D_ + f];
        s += v; s2 += v * v;
    }
#pragma unroll
    for (int off = 16; off > 0; off >>= 1) {
        s  += __shfl_down_sync(0xffffffffu, s,  off);
        s2 += __shfl_down_sync(0xffffffffu, s2, off);
    }
    __shared__ float ws[8], ws2[8];
    if ((tid & 31) == 0) { ws[tid >> 5] = s; ws2[tid >> 5] = s2; }
    __syncthreads();
    if (tid == 0) {
        float S = 0.f, S2 = 0.f;
#pragma unroll
        for (int i = 0; i < 8; i++) { S += ws[i]; S2 += ws2[i]; }
        float mu  = S / (float)M_;
        float var = S2 / (float)M_ - mu * mu;
        g_mu[f]   = mu;
        g_rstd[f] = rsqrtf(var + EPS_);
    }
}

// =================================================================
// Kernel 3: BN affine + ReLU*mask + adds -> d_out
// =================================================================
__global__ __launch_bounds__(256) void apply_k(const float* __restrict__ gamma,
                                               const float* __restrict__ beta,
                                               const float* __restrict__ mask,
                                               const float* __restrict__ residual,
                                               const float* __restrict__ attention,
                                               const float* __restrict__ positional,
                                               float* __restrict__ out)
{
    const int n4 = (M_ * D_) / 4;
    for (int i = blockIdx.x * blockDim.x + threadIdx.x; i < n4;
         i += gridDim.x * blockDim.x) {
        const int f4 = i & (D_ / 4 - 1);
        float4 hv = ((const float4*)g_h0)[i];
        float4 g  = ((const float4*)gamma)[f4];
        float4 bt = ((const float4*)beta)[f4];
        float4 mu = ((const float4*)g_mu)[f4];
        float4 rs = ((const float4*)g_rstd)[f4];
        float4 mk = ((const float4*)mask)[i];
        float4 rd = ((const float4*)residual)[i];
        float4 at = ((const float4*)attention)[i];
        float4 ps = ((const float4*)positional)[i];
        float4 y;
        y.x = fmaxf(g.x * (hv.x - mu.x) * rs.x + bt.x, 0.f) * mk.x + rd.x + at.x + ps.x;
        y.y = fmaxf(g.y * (hv.y - mu.y) * rs.y + bt.y, 0.f) * mk.y + rd.y + at.y + ps.y;
        y.z = fmaxf(g.z * (hv.z - mu.z) * rs.z + bt.z, 0.f) * mk.z + rd.z + at.z + ps.z;
        y.w = fmaxf(g.w * (hv.w - mu.w) * rs.w + bt.w, 0.f) * mk.w + rd.w + at.w + ps.w;
        ((float4*)out)[i] = y;
    }
}

// =================================================================
// Kernel 4 (x6): flash-attention, 4-lane group / 2 rows per group.
// Lane c = tid&3 owns 16B units {c, c+4, c+8, c+12} of TWO query
// rows. Each K/V unit loaded ONCE serves both rows: LDS per warp
// per key halves (16 -> 8) vs the lane-pair version, attacking the
// measured L1tex=85.8% bottleneck. FFMA2 count unchanged (MAC floor).
// Score reduced across the 4-lane group with shfl_xor 1 then 2
// (commutative fp32 adds -> all 4 lanes bitwise identical -> m/l
// lock-step -> deterministic). o-rescale guarded by __any_sync
// (skipped only when every row's corr == 1.0 exactly).
// In-place h update race-free (disjoint rows/units per thread).
// =================================================================
#define QT2 64   // query rows per block (32 groups x 2 rows)
#define KT  32   // keys per smem tile
#define KH  4    // score batch

__global__ __launch_bounds__(128, 4) void flash_k(float* __restrict__ h,
                                                  const float* __restrict__ qb,
                                                  const float* __restrict__ kb,
                                                  const float* __restrict__ vb)
{
    // [buf][K=0/V=1][key][16B-unit]  : 2*2*32*16*16B = 32 KB
    __shared__ F4U2 KVs[2][2][KT][DH_ / 4];

    const int tid = threadIdx.x;
    const int c   = tid & 3;             // unit slot within group
    const int grp = tid >> 2;            // 0..31 (global group in block)
    const int ra  = blockIdx.x * QT2 + grp * 2;   // first of 2 rows
    const int hh  = blockIdx.y;
    const int b   = blockIdx.z;
    const size_t rowoff_a = ((size_t)(b * S_ + ra)) * D_ + hh * DH_;
    const size_t rowoff_b = rowoff_a + D_;        // row ra+1
    const size_t headoff  = ((size_t)b * S_) * D_ + hh * DH_;

    // 4 16B-units per row -> 8 packed f32x2 regs per row for q and o
    ull q2a[8], q2b[8], o2a[8], o2b[8];
    {
        const F4U2* ha = (const F4U2*)(h + rowoff_a);
        const F4U2* qa = (const F4U2*)(qb + rowoff_a);
        const F4U2* hb = (const F4U2*)(h + rowoff_b);
        const F4U2* qbp = (const F4U2*)(qb + rowoff_b);
#pragma unroll
        for (int i = 0; i < 4; i++) {
            const int u = c + 4 * i;
            F4U2 xa = ha[u], ya = qa[u];
            F4U2 xb = hb[u], yb = qbp[u];
            q2a[2 * i]     = d_add2(xa.u.x, ya.u.x);
            q2a[2 * i + 1] = d_add2(xa.u.y, ya.u.y);
            q2b[2 * i]     = d_add2(xb.u.x, yb.u.x);
            q2b[2 * i + 1] = d_add2(xb.u.y, yb.u.y);
            o2a[2 * i] = 0ull; o2a[2 * i + 1] = 0ull;
            o2b[2 * i] = 0ull; o2b[2 * i + 1] = 0ull;
        }
    }
    float m_a = -1e30f, l_a = 0.f;
    float m_b = -1e30f, l_b = 0.f;

    // loader: 1024 16B units per tile (K:512, V:512), 8 per thread
    auto load_tile = [&](int kt, int bf) {
#pragma unroll
        for (int li = 0; li < 8; li++) {
            int idx = tid + li * 128;          // 0..1023
            int kv  = idx >> 9;                // 0:K 1:V
            int j   = (idx >> 4) & 31;
            int u   = idx & 15;
            const float* gsrc = (kv ? vb : kb) + headoff
                              + (size_t)(kt + j) * D_ + u * 4;
            cp16((unsigned int)__cvta_generic_to_shared(&KVs[bf][kv][j][u]), gsrc);
        }
        asm volatile("cp.async.commit_group;" ::: "memory");
    };

    load_tile(0, 0);

    for (int kt = 0, t = 0; kt < S_; kt += KT, t++) {
        asm volatile("cp.async.wait_group 0;" ::: "memory");
        __syncthreads();
        if (kt + KT < S_) load_tile(kt + KT, (t + 1) & 1);
        const int bf = t & 1;
        const F4U2 (*Ks)[DH_ / 4] = KVs[bf][0];
        const F4U2 (*Vs)[DH_ / 4] = KVs[bf][1];

#pragma unroll
        for (int batch = 0; batch < KT / KH; batch++) {
            const int jb = batch * KH;
            float pa[KH], pb[KH];
            // partial scores: one K load serves both rows
#pragma unroll
            for (int j = 0; j < KH; j++) {
                const F4U2* kr = Ks[jb + j];
                F4U2 k0 = kr[c], k1 = kr[c + 4], k2 = kr[c + 8], k3 = kr[c + 12];
                ull s0 = d_fma2(q2a[0], k0.u.x, 0ull);
                ull s1 = d_fma2(q2a[1], k0.u.y, 0ull);
                s0 = d_fma2(q2a[2], k1.u.x, s0);
                s1 = d_fma2(q2a[3], k1.u.y, s1);
                s0 = d_fma2(q2a[4], k2.u.x, s0);
                s1 = d_fma2(q2a[5], k2.u.y, s1);
                s0 = d_fma2(q2a[6], k3.u.x, s0);
                s1 = d_fma2(q2a[7], k3.u.y, s1);
                s0 = d_add2(s0, s1);
                float2 fa = unpack2(s0);
                pa[j] = fa.x + fa.y;

                ull t0 = d_fma2(q2b[0], k0.u.x, 0ull);
                ull t1 = d_fma2(q2b[1], k0.u.y, 0ull);
                t0 = d_fma2(q2b[2], k1.u.x, t0);
                t1 = d_fma2(q2b[3], k1.u.y, t1);
                t0 = d_fma2(q2b[4], k2.u.x, t0);
                t1 = d_fma2(q2b[5], k2.u.y, t1);
                t0 = d_fma2(q2b[6], k3.u.x, t0);
                t1 = d_fma2(q2b[7], k3.u.y, t1);
                t0 = d_add2(t0, t1);
                float2 fb = unpack2(t0);
                pb[j] = fb.x + fb.y;
            }
            // combine 4-lane partials (independent shuffles, pipelined)
            float mna = m_a, mnb = m_b;
#pragma unroll
            for (int j = 0; j < KH; j++) {
                pa[j] += __shfl_xor_sync(0xffffffffu, pa[j], 1);
                pb[j] += __shfl_xor_sync(0xffffffffu, pb[j], 1);
                pa[j] += __shfl_xor_sync(0xffffffffu, pa[j], 2);
                pb[j] += __shfl_xor_sync(0xffffffffu, pb[j], 2);
                pa[j] *= 0.125f;               // 1/sqrt(64)
                pb[j] *= 0.125f;
                mna = fmaxf(mna, pa[j]);
                mnb = fmaxf(mnb, pb[j]);
            }
            // rescale only when some row's max moved (skipped corr == 1)
            if (__any_sync(0xffffffffu, (mna > m_a) || (mnb > m_b))) {
                float ca = __expf(m_a - mna);
                float cb = __expf(m_b - mnb);
                l_a *= ca; l_b *= cb;
                ull cca = pack2(ca, ca), ccb = pack2(cb, cb);
#pragma unroll
                for (int i = 0; i < 8; i++) {
                    o2a[i] = d_mul2(o2a[i], cca);
                    o2b[i] = d_mul2(o2b[i], ccb);
                }
                m_a = mna; m_b = mnb;
            }
#pragma unroll
            for (int j = 0; j < KH; j++) {
                float pja = __expf(pa[j] - m_a);
                float pjb = __expf(pb[j] - m_b);
                l_a += pja; l_b += pjb;
                ull ppa = pack2(pja, pja), ppb = pack2(pjb, pjb);
                const F4U2* vr = Vs[jb + j];
                F4U2 v0 = vr[c], v1 = vr[c + 4], v2 = vr[c + 8], v3 = vr[c + 12];
                o2a[0] = d_fma2(ppa, v0.u.x, o2a[0]);
                o2a[1] = d_fma2(ppa, v0.u.y, o2a[1]);
                o2a[2] = d_fma2(ppa, v1.u.x, o2a[2]);
                o2a[3] = d_fma2(ppa, v1.u.y, o2a[3]);
                o2a[4] = d_fma2(ppa, v2.u.x, o2a[4]);
                o2a[5] = d_fma2(ppa, v2.u.y, o2a[5]);
                o2a[6] = d_fma2(ppa, v3.u.x, o2a[6]);
                o2a[7] = d_fma2(ppa, v3.u.y, o2a[7]);
                o2b[0] = d_fma2(ppb, v0.u.x, o2b[0]);
                o2b[1] = d_fma2(ppb, v0.u.y, o2b[1]);
                o2b[2] = d_fma2(ppb, v1.u.x, o2b[2]);
                o2b[3] = d_fma2(ppb, v1.u.y, o2b[3]);
                o2b[4] = d_fma2(ppb, v2.u.x, o2b[4]);
                o2b[5] = d_fma2(ppb, v2.u.y, o2b[5]);
                o2b[6] = d_fma2(ppb, v3.u.x, o2b[6]);
                o2b[7] = d_fma2(ppb, v3.u.y, o2b[7]);
            }
        }
    }

    const float inv_a = 1.f / l_a;
    const float inv_b = 1.f / l_b;
    F4U2* hwa = (F4U2*)(h + rowoff_a);
    F4U2* hwb = (F4U2*)(h + rowoff_b);
#pragma unroll
    for (int i = 0; i < 4; i++) {
        const int u = c + 4 * i;
        F4U2 xa = hwa[u];
        float2 e0 = unpack2(o2a[2 * i]);
        float2 e1 = unpack2(o2a[2 * i + 1]);
        xa.f.x += e0.x * inv_a; xa.f.y += e0.y * inv_a;
        xa.f.z += e1.x * inv_a; xa.f.w += e1.y * inv_a;
        hwa[u] = xa;
        F4U2 xb = hwb[u];
        float2 g0 = unpack2(o2b[2 * i]);
        float2 g1 = unpack2(o2b[2 * i + 1]);
        xb.f.x += g0.x * inv_b; xb.f.y += g0.y * inv_b;
        xb.f.z += g1.x * inv_b; xb.f.w += g1.y * inv_b;
        hwb[u] = xb;
    }
}

// =================================================================
// launch
// =================================================================
extern "C" void kernel_launch(void* const* d_in, const int* in_sizes, int n_in,
                              void* d_out, int out_size)
{
    const float* x          = (const float*)d_in[0];
    const float* W          = (const float*)d_in[1];
    const float* scale      = (const float*)d_in[2];
    const float* gamma      = (const float*)d_in[3];
    const float* beta       = (const float*)d_in[4];
    const float* mask       = (const float*)d_in[5];
    const float* residual   = (const float*)d_in[6];
    const float* attention  = (const float*)d_in[7];
    const float* positional = (const float*)d_in[8];
    float* out = (float*)d_out;

    dim3 gg(D_ / BN, M_ / BM);
    gemm_k<<<gg, 256>>>(x, W, scale);

    stats_k<<<D_, 256>>>();

    apply_k<<<2048, 256>>>(gamma, beta, mask, residual, attention, positional, out);

    dim3 fg(S_ / QT2, H_, B_);              // (16, 16, 4) = 1024 blocks
    for (int t = 0; t < 6; t++) {
        flash_k<<<fg, 128>>>(out,
                             (const float*)d_in[9  + 3 * t],
                             (const float*)d_in[10 + 3 * t],
                             (const float*)d_in[11 + 3 * t]);
    }
}

// round 16
// speedup vs baseline: 2.0497x; 2.0497x over previous
#include <cuda_runtime.h>
#include <cuda_bf16.h>
#include <math.h>
#include <stdint.h>

#define B_  4
#define S_  1024
#define D_  1024
#define H_  16
#define DH_ 64
#define M_  (B_*S_)
#define EPS_ 1e-5f

// ---------------- scratch (no allocations allowed) ----------------
__device__ __align__(16) float g_h0[M_ * D_];
__device__ __align__(16) float g_mu[D_];
__device__ __align__(16) float g_rstd[D_];

// =================================================================
// Kernel 1: h0[m,n] = scale[n] * sum_k x[m,k] * W[n,k]
// =================================================================
#define BM 64
#define BN 64
#define BK 16

__global__ __launch_bounds__(256) void gemm_k(const float* __restrict__ x,
                                              const float* __restrict__ W,
                                              const float* __restrict__ scale)
{
    __shared__ float As[BK][BM];
    __shared__ float Bs[BK][BN];

    const int m0  = blockIdx.y * BM;
    const int n0  = blockIdx.x * BN;
    const int tid = threadIdx.x;
    const int lrow = tid >> 2;
    const int lk   = (tid & 3) << 2;
    const int tx = tid & 15;
    const int ty = tid >> 4;

    float acc[4][4];
#pragma unroll
    for (int i = 0; i < 4; i++)
#pragma unroll
        for (int j = 0; j < 4; j++) acc[i][j] = 0.f;

    const float* xg = x + (size_t)(m0 + lrow) * D_;
    const float* wg = W + (size_t)(n0 + lrow) * D_;

    for (int k0 = 0; k0 < D_; k0 += BK) {
        float4 a = *(const float4*)(xg + k0 + lk);
        float4 b = *(const float4*)(wg + k0 + lk);
        __syncthreads();
        As[lk + 0][lrow] = a.x; As[lk + 1][lrow] = a.y;
        As[lk + 2][lrow] = a.z; As[lk + 3][lrow] = a.w;
        Bs[lk + 0][lrow] = b.x; Bs[lk + 1][lrow] = b.y;
        Bs[lk + 2][lrow] = b.z; Bs[lk + 3][lrow] = b.w;
        __syncthreads();
#pragma unroll
        for (int k = 0; k < BK; k++) {
            float4 av = *(const float4*)&As[k][ty << 2];
            float4 bv = *(const float4*)&Bs[k][tx << 2];
            acc[0][0] += av.x * bv.x; acc[0][1] += av.x * bv.y;
            acc[0][2] += av.x * bv.z; acc[0][3] += av.x * bv.w;
            acc[1][0] += av.y * bv.x; acc[1][1] += av.y * bv.y;
            acc[1][2] += av.y * bv.z; acc[1][3] += av.y * bv.w;
            acc[2][0] += av.z * bv.x; acc[2][1] += av.z * bv.y;
            acc[2][2] += av.z * bv.z; acc[2][3] += av.z * bv.w;
            acc[3][0] += av.w * bv.x; acc[3][1] += av.w * bv.y;
            acc[3][2] += av.w * bv.z; acc[3][3] += av.w * bv.w;
        }
    }

    const int nc = n0 + (tx << 2);
    float4 sc = *(const float4*)(scale + nc);
#pragma unroll
    for (int i = 0; i < 4; i++) {
        const int row = m0 + (ty << 2) + i;
        float4 o;
        o.x = acc[i][0] * sc.x; o.y = acc[i][1] * sc.y;
        o.z = acc[i][2] * sc.z; o.w = acc[i][3] * sc.w;
        *(float4*)&g_h0[(size_t)row * D_ + nc] = o;
    }
}

// =================================================================
// Kernel 2: per-feature mean / rstd
// =================================================================
__global__ __launch_bounds__(256) void stats_k()
{
    const int f = blockIdx.x;
    const int tid = threadIdx.x;
    float s = 0.f, s2 = 0.f;
    for (int r = tid; r < M_; r += 256) {
        float v = g_h0[(size_t)r * D_ + f];
        s += v; s2 += v * v;
    }
#pragma unroll
    for (int off = 16; off > 0; off >>= 1) {
        s  += __shfl_down_sync(0xffffffffu, s,  off);
        s2 += __shfl_down_sync(0xffffffffu, s2, off);
    }
    __shared__ float ws[8], ws2[8];
    if ((tid & 31) == 0) { ws[tid >> 5] = s; ws2[tid >> 5] = s2; }
    __syncthreads();
    if (tid == 0) {
        float S = 0.f, S2 = 0.f;
#pragma unroll
        for (int i = 0; i < 8; i++) { S += ws[i]; S2 += ws2[i]; }
        float mu  = S / (float)M_;
        float var = S2 / (float)M_ - mu * mu;
        g_mu[f]   = mu;
        g_rstd[f] = rsqrtf(var + EPS_);
    }
}

// =================================================================
// Kernel 3: BN affine + ReLU*mask + adds -> d_out
// =================================================================
__global__ __launch_bounds__(256) void apply_k(const float* __restrict__ gamma,
                                               const float* __restrict__ beta,
                                               const float* __restrict__ mask,
                                               const float* __restrict__ residual,
                                               const float* __restrict__ attention,
                                               const float* __restrict__ positional,
                                               float* __restrict__ out)
{
    const int n4 = (M_ * D_) / 4;
    for (int i = blockIdx.x * blockDim.x + threadIdx.x; i < n4;
         i += gridDim.x * blockDim.x) {
        const int f4 = i & (D_ / 4 - 1);
        float4 hv = ((const float4*)g_h0)[i];
        float4 g  = ((const float4*)gamma)[f4];
        float4 bt = ((const float4*)beta)[f4];
        float4 mu = ((const float4*)g_mu)[f4];
        float4 rs = ((const float4*)g_rstd)[f4];
        float4 mk = ((const float4*)mask)[i];
        float4 rd = ((const float4*)residual)[i];
        float4 at = ((const float4*)attention)[i];
        float4 ps = ((const float4*)positional)[i];
        float4 y;
        y.x = fmaxf(g.x * (hv.x - mu.x) * rs.x + bt.x, 0.f) * mk.x + rd.x + at.x + ps.x;
        y.y = fmaxf(g.y * (hv.y - mu.y) * rs.y + bt.y, 0.f) * mk.y + rd.y + at.y + ps.y;
        y.z = fmaxf(g.z * (hv.z - mu.z) * rs.z + bt.z, 0.f) * mk.z + rd.z + at.z + ps.z;
        y.w = fmaxf(g.w * (hv.w - mu.w) * rs.w + bt.w, 0.f) * mk.w + rd.w + at.w + ps.w;
        ((float4*)out)[i] = y;
    }
}

// =================================================================
// helpers (baseline PTX only: mma.sync + ldmatrix, sm_80+)
// =================================================================
__device__ __forceinline__ uint32_t u32s(const void* p) {
    uint32_t a;
    asm("{ .reg .u64 t; cvta.to.shared.u64 t, %1; cvt.u32.u64 %0, t; }"
        : "=r"(a) : "l"(p));
    return a;
}
// bf16 round of x, returned as float
__device__ __forceinline__ float bff(float x) {
    unsigned short hsh;
    asm("cvt.rn.bf16.f32 %0, %1;" : "=h"(hsh) : "f"(x));
    return __uint_as_float(((uint32_t)hsh) << 16);
}
// pack two floats -> bf16x2 {low = a, high = b}
__device__ __forceinline__ uint32_t bf2(float a, float b) {
    uint32_t r;
    asm("cvt.rn.bf16x2.f32 %0, %1, %2;" : "=r"(r) : "f"(b), "f"(a));
    return r;
}
__device__ __forceinline__ void mma16816(float* d, const uint32_t* a,
                                         uint32_t b0, uint32_t b1) {
    asm volatile("mma.sync.aligned.m16n8k16.row.col.f32.bf16.bf16.f32 "
                 "{%0,%1,%2,%3}, {%4,%5,%6,%7}, {%8,%9}, {%0,%1,%2,%3};"
                 : "+f"(d[0]), "+f"(d[1]), "+f"(d[2]), "+f"(d[3])
                 : "r"(a[0]), "r"(a[1]), "r"(a[2]), "r"(a[3]),
                   "r"(b0), "r"(b1));
}
__device__ __forceinline__ void ldm4(uint32_t* r, uint32_t addr) {
    asm volatile("ldmatrix.sync.aligned.m8n8.x4.shared.b16 {%0,%1,%2,%3}, [%4];"
                 : "=r"(r[0]), "=r"(r[1]), "=r"(r[2]), "=r"(r[3]) : "r"(addr));
}
__device__ __forceinline__ void ldm4t(uint32_t* r, uint32_t addr) {
    asm volatile("ldmatrix.sync.aligned.m8n8.x4.trans.shared.b16 {%0,%1,%2,%3}, [%4];"
                 : "=r"(r[0]), "=r"(r[1]), "=r"(r[2]), "=r"(r[3]) : "r"(addr));
}
#define SWZ(o) ((o) ^ (((o) >> 3) & 0x70))

// =================================================================
// Kernel 4 (x6): flash attention on HMMA (mma.sync m16n8k16 bf16,
// split hi/lo for fp32-grade accuracy; 3 products, lo*lo dropped).
// Block = 64 query rows x 1 head; warp owns 16 rows (one m16 tile).
// Per 64-key chunk: K,V -> smem bf16 hi/lo (SW128); S = Q*K^T via
// ldmatrix(x4) + mma; fixed-m0 softmax in fragment registers (C-frag
// -> A-frag mapping is lane-identity: no shuffles); O += P*V via
// ldmatrix.x4.trans. O in fp32 fragments across all chunks.
// =================================================================
#define QROWS 64

__global__ __launch_bounds__(128, 2) void attn_mma(float* __restrict__ h,
                                                   const float* __restrict__ qb,
                                                   const float* __restrict__ kb,
                                                   const float* __restrict__ vb)
{
    __shared__ __align__(1024) unsigned char sKhi[64 * 128];
    __shared__ __align__(1024) unsigned char sKlo[64 * 128];
    __shared__ __align__(1024) unsigned char sVhi[64 * 128];
    __shared__ __align__(1024) unsigned char sVlo[64 * 128];

    const int tid  = threadIdx.x;
    const int lane = tid & 31;
    const int warp = tid >> 5;
    const int hh   = blockIdx.y;
    const int b    = blockIdx.z;
    const int r0   = blockIdx.x * QROWS;

    const size_t headoff = ((size_t)b * S_) * D_ + hh * DH_;
    const int    qrow0   = r0 + warp * 16 + (lane >> 2);
    const size_t row0off = headoff + (size_t)qrow0 * D_;
    const int    cb      = (lane & 3) * 2;

    // ---- Q fragments (built once): rows qrow0, qrow0+8 ----
    uint32_t QH[4][4], QL[4][4];
    {
        const float* h0 = h + row0off;
        const float* q0 = qb + row0off;
        const float* h1 = h0 + 8 * (size_t)D_;
        const float* q1 = q0 + 8 * (size_t)D_;
#pragma unroll
        for (int s = 0; s < 4; s++) {
            int c0 = s * 16 + cb, c1 = c0 + 8;
            float2 xa = *(const float2*)(h0 + c0), ya = *(const float2*)(q0 + c0);
            float2 xb = *(const float2*)(h1 + c0), yb = *(const float2*)(q1 + c0);
            float2 xc = *(const float2*)(h0 + c1), yc = *(const float2*)(q0 + c1);
            float2 xd = *(const float2*)(h1 + c1), yd = *(const float2*)(q1 + c1);
            float a0 = xa.x + ya.x, a1 = xa.y + ya.y;
            float b0 = xb.x + yb.x, b1 = xb.y + yb.y;
            float c0f = xc.x + yc.x, c1f = xc.y + yc.y;
            float d0 = xd.x + yd.x, d1 = xd.y + yd.y;
            QH[s][0] = bf2(a0, a1);  QL[s][0] = bf2(a0 - bff(a0), a1 - bff(a1));
            QH[s][1] = bf2(b0, b1);  QL[s][1] = bf2(b0 - bff(b0), b1 - bff(b1));
            QH[s][2] = bf2(c0f, c1f); QL[s][2] = bf2(c0f - bff(c0f), c1f - bff(c1f));
            QH[s][3] = bf2(d0, d1);  QL[s][3] = bf2(d0 - bff(d0), d1 - bff(d1));
        }
    }

    float O[8][4];
#pragma unroll
    for (int t = 0; t < 8; t++)
#pragma unroll
        for (int j = 0; j < 4; j++) O[t][j] = 0.f;
    float l0 = 0.f, l1 = 0.f, m0a = 0.f, m0b = 0.f;

    const uint32_t bKhi = u32s(sKhi), bKlo = u32s(sKlo);
    const uint32_t bVhi = u32s(sVhi), bVlo = u32s(sVlo);
    const int lkey = tid >> 1, lhf = tid & 1;

    for (int ch = 0; ch < 16; ch++) {
        __syncthreads();   // previous chunk compute done before overwrite
        // ---- K,V chunk -> smem (bf16 hi/lo, SW128) ----
        {
            const float4* gK = (const float4*)(kb + headoff + (size_t)(ch * 64 + lkey) * D_ + lhf * 32);
            const float4* gV = (const float4*)(vb + headoff + (size_t)(ch * 64 + lkey) * D_ + lhf * 32);
            uint32_t base = lkey * 128 + lhf * 64;
#pragma unroll
            for (int u = 0; u < 4; u++) {
                uint32_t off = SWZ(base + u * 16);
                float4 f0 = gK[u * 2], f1 = gK[u * 2 + 1];
                uint4 HI, LO;
                HI.x = bf2(f0.x, f0.y); HI.y = bf2(f0.z, f0.w);
                HI.z = bf2(f1.x, f1.y); HI.w = bf2(f1.z, f1.w);
                LO.x = bf2(f0.x - bff(f0.x), f0.y - bff(f0.y));
                LO.y = bf2(f0.z - bff(f0.z), f0.w - bff(f0.w));
                LO.z = bf2(f1.x - bff(f1.x), f1.y - bff(f1.y));
                LO.w = bf2(f1.z - bff(f1.z), f1.w - bff(f1.w));
                *(uint4*)(sKhi + off) = HI; *(uint4*)(sKlo + off) = LO;
                f0 = gV[u * 2]; f1 = gV[u * 2 + 1];
                HI.x = bf2(f0.x, f0.y); HI.y = bf2(f0.z, f0.w);
                HI.z = bf2(f1.x, f1.y); HI.w = bf2(f1.z, f1.w);
                LO.x = bf2(f0.x - bff(f0.x), f0.y - bff(f0.y));
                LO.y = bf2(f0.z - bff(f0.z), f0.w - bff(f0.w));
                LO.z = bf2(f1.x - bff(f1.x), f1.y - bff(f1.y));
                LO.w = bf2(f1.z - bff(f1.z), f1.w - bff(f1.w));
                *(uint4*)(sVhi + off) = HI; *(uint4*)(sVlo + off) = LO;
            }
        }
        __syncthreads();

        // ---- S = Q * K^T (8 key-tiles x 4 k-steps x 3 splits) ----
        float Sacc[8][4];
#pragma unroll
        for (int t = 0; t < 8; t++)
#pragma unroll
            for (int j = 0; j < 4; j++) Sacc[t][j] = 0.f;

#pragma unroll
        for (int s = 0; s < 4; s++) {
            uint32_t kh[4][4], kl[4][4];
#pragma unroll
            for (int tp = 0; tp < 4; tp++) {
                int m = lane >> 3;
                uint32_t key  = tp * 16 + (m >> 1) * 8 + (lane & 7);
                uint32_t byte = key * 128 + s * 32 + (m & 1) * 16;
                ldm4(kh[tp], bKhi + SWZ(byte));
                ldm4(kl[tp], bKlo + SWZ(byte));
            }
#pragma unroll
            for (int t = 0; t < 8; t++) {
                uint32_t b0h = kh[t >> 1][(t & 1) * 2], b1h = kh[t >> 1][(t & 1) * 2 + 1];
                uint32_t b0l = kl[t >> 1][(t & 1) * 2], b1l = kl[t >> 1][(t & 1) * 2 + 1];
                mma16816(Sacc[t], QH[s], b0h, b1h);
                mma16816(Sacc[t], QH[s], b0l, b1l);
                mma16816(Sacc[t], QL[s], b0h, b1h);
            }
        }

        if (ch == 0) {
            float ma = -1e30f, mb = -1e30f;
#pragma unroll
            for (int t = 0; t < 8; t++) {
                ma = fmaxf(ma, fmaxf(Sacc[t][0], Sacc[t][1]));
                mb = fmaxf(mb, fmaxf(Sacc[t][2], Sacc[t][3]));
            }
            ma = fmaxf(ma, __shfl_xor_sync(0xffffffffu, ma, 1));
            ma = fmaxf(ma, __shfl_xor_sync(0xffffffffu, ma, 2));
            mb = fmaxf(mb, __shfl_xor_sync(0xffffffffu, mb, 1));
            mb = fmaxf(mb, __shfl_xor_sync(0xffffffffu, mb, 2));
            m0a = ma * 0.125f;
            m0b = mb * 0.125f;
        }

        // ---- O += P * V (P built in-lane: C-frag == A-frag layout) ----
#pragma unroll
        for (int s = 0; s < 4; s++) {
            float p00 = __expf(Sacc[2 * s][0] * 0.125f - m0a);
            float p01 = __expf(Sacc[2 * s][1] * 0.125f - m0a);
            float p02 = __expf(Sacc[2 * s][2] * 0.125f - m0b);
            float p03 = __expf(Sacc[2 * s][3] * 0.125f - m0b);
            float p10 = __expf(Sacc[2 * s + 1][0] * 0.125f - m0a);
            float p11 = __expf(Sacc[2 * s + 1][1] * 0.125f - m0a);
            float p12 = __expf(Sacc[2 * s + 1][2] * 0.125f - m0b);
            float p13 = __expf(Sacc[2 * s + 1][3] * 0.125f - m0b);
            l0 += p00 + p01 + p10 + p11;
            l1 += p02 + p03 + p12 + p13;
            uint32_t PHI[4], PLO[4];
            PHI[0] = bf2(p00, p01); PLO[0] = bf2(p00 - bff(p00), p01 - bff(p01));
            PHI[1] = bf2(p02, p03); PLO[1] = bf2(p02 - bff(p02), p03 - bff(p03));
            PHI[2] = bf2(p10, p11); PLO[2] = bf2(p10 - bff(p10), p11 - bff(p11));
            PHI[3] = bf2(p12, p13); PLO[3] = bf2(p12 - bff(p12), p13 - bff(p13));
#pragma unroll
            for (int tp = 0; tp < 4; tp++) {
                int m = lane >> 3;
                uint32_t key  = s * 16 + (m & 1) * 8 + (lane & 7);
                uint32_t byte = key * 128 + tp * 32 + (m >> 1) * 16;
                uint32_t vh[4], vl[4];
                ldm4t(vh, bVhi + SWZ(byte));
                ldm4t(vl, bVlo + SWZ(byte));
#pragma unroll
                for (int tt = 0; tt < 2; tt++) {
                    int t = 2 * tp + tt;
                    uint32_t b0h = vh[tt * 2], b1h = vh[tt * 2 + 1];
                    uint32_t b0l = vl[tt * 2], b1l = vl[tt * 2 + 1];
                    mma16816(O[t], PHI, b0h, b1h);
                    mma16816(O[t], PHI, b0l, b1l);
                    mma16816(O[t], PLO, b0h, b1h);
                }
            }
        }
    }

    // ---- epilogue: h[row] += O/l ----
    l0 += __shfl_xor_sync(0xffffffffu, l0, 1);
    l0 += __shfl_xor_sync(0xffffffffu, l0, 2);
    l1 += __shfl_xor_sync(0xffffffffu, l1, 1);
    l1 += __shfl_xor_sync(0xffffffffu, l1, 2);
    const float inv0 = 1.f / l0, inv1 = 1.f / l1;

    float* ho0 = h + row0off;
    float* ho1 = ho0 + 8 * (size_t)D_;
#pragma unroll
    for (int t = 0; t < 8; t++) {
        int c = t * 8 + cb;
        float2 v0 = *(float2*)(ho0 + c);
        v0.x += O[t][0] * inv0; v0.y += O[t][1] * inv0;
        *(float2*)(ho0 + c) = v0;
        float2 v1 = *(float2*)(ho1 + c);
        v1.x += O[t][2] * inv1; v1.y += O[t][3] * inv1;
        *(float2*)(ho1 + c) = v1;
    }
}

// =================================================================
// launch
// =================================================================
extern "C" void kernel_launch(void* const* d_in, const int* in_sizes, int n_in,
                              void* d_out, int out_size)
{
    const float* x          = (const float*)d_in[0];
    const float* W          = (const float*)d_in[1];
    const float* scale      = (const float*)d_in[2];
    const float* gamma      = (const float*)d_in[3];
    const float* beta       = (const float*)d_in[4];
    const float* mask       = (const float*)d_in[5];
    const float* residual   = (const float*)d_in[6];
    const float* attention  = (const float*)d_in[7];
    const float* positional = (const float*)d_in[8];
    float* out = (float*)d_out;

    dim3 gg(D_ / BN, M_ / BM);
    gemm_k<<<gg, 256>>>(x, W, scale);

    stats_k<<<D_, 256>>>();

    apply_k<<<2048, 256>>>(gamma, beta, mask, residual, attention, positional, out);

    dim3 fg(S_ / QROWS, H_, B_);            // (16, 16, 4) = 1024 blocks
    for (int t = 0; t < 6; t++) {
        attn_mma<<<fg, 128>>>(out,
                              (const float*)d_in[9  + 3 * t],
                              (const float*)d_in[10 + 3 * t],
                              (const float*)d_in[11 + 3 * t]);
    }
}

// round 17
// speedup vs baseline: 2.3949x; 1.1684x over previous
#include <cuda_runtime.h>
#include <cuda_bf16.h>
#include <math.h>
#include <stdint.h>

#define B_  4
#define S_  1024
#define D_  1024
#define H_  16
#define DH_ 64
#define M_  (B_*S_)
#define EPS_ 1e-5f

// ---------------- scratch (no allocations allowed) ----------------
__device__ __align__(16) float g_h0[M_ * D_];
__device__ __align__(16) float g_mu[D_];
__device__ __align__(16) float g_rstd[D_];

// =================================================================
// Kernel 1: h0[m,n] = scale[n] * sum_k x[m,k] * W[n,k]
// =================================================================
#define BM 64
#define BN 64
#define BK 16

__global__ __launch_bounds__(256) void gemm_k(const float* __restrict__ x,
                                              const float* __restrict__ W,
                                              const float* __restrict__ scale)
{
    __shared__ float As[BK][BM];
    __shared__ float Bs[BK][BN];

    const int m0  = blockIdx.y * BM;
    const int n0  = blockIdx.x * BN;
    const int tid = threadIdx.x;
    const int lrow = tid >> 2;
    const int lk   = (tid & 3) << 2;
    const int tx = tid & 15;
    const int ty = tid >> 4;

    float acc[4][4];
#pragma unroll
    for (int i = 0; i < 4; i++)
#pragma unroll
        for (int j = 0; j < 4; j++) acc[i][j] = 0.f;

    const float* xg = x + (size_t)(m0 + lrow) * D_;
    const float* wg = W + (size_t)(n0 + lrow) * D_;

    for (int k0 = 0; k0 < D_; k0 += BK) {
        float4 a = *(const float4*)(xg + k0 + lk);
        float4 b = *(const float4*)(wg + k0 + lk);
        __syncthreads();
        As[lk + 0][lrow] = a.x; As[lk + 1][lrow] = a.y;
        As[lk + 2][lrow] = a.z; As[lk + 3][lrow] = a.w;
        Bs[lk + 0][lrow] = b.x; Bs[lk + 1][lrow] = b.y;
        Bs[lk + 2][lrow] = b.z; Bs[lk + 3][lrow] = b.w;
        __syncthreads();
#pragma unroll
        for (int k = 0; k < BK; k++) {
            float4 av = *(const float4*)&As[k][ty << 2];
            float4 bv = *(const float4*)&Bs[k][tx << 2];
            acc[0][0] += av.x * bv.x; acc[0][1] += av.x * bv.y;
            acc[0][2] += av.x * bv.z; acc[0][3] += av.x * bv.w;
            acc[1][0] += av.y * bv.x; acc[1][1] += av.y * bv.y;
            acc[1][2] += av.y * bv.z; acc[1][3] += av.y * bv.w;
            acc[2][0] += av.z * bv.x; acc[2][1] += av.z * bv.y;
            acc[2][2] += av.z * bv.z; acc[2][3] += av.z * bv.w;
            acc[3][0] += av.w * bv.x; acc[3][1] += av.w * bv.y;
            acc[3][2] += av.w * bv.z; acc[3][3] += av.w * bv.w;
        }
    }

    const int nc = n0 + (tx << 2);
    float4 sc = *(const float4*)(scale + nc);
#pragma unroll
    for (int i = 0; i < 4; i++) {
        const int row = m0 + (ty << 2) + i;
        float4 o;
        o.x = acc[i][0] * sc.x; o.y = acc[i][1] * sc.y;
        o.z = acc[i][2] * sc.z; o.w = acc[i][3] * sc.w;
        *(float4*)&g_h0[(size_t)row * D_ + nc] = o;
    }
}

// =================================================================
// Kernel 2: per-feature mean / rstd
// =================================================================
__global__ __launch_bounds__(256) void stats_k()
{
    const int f = blockIdx.x;
    const int tid = threadIdx.x;
    float s = 0.f, s2 = 0.f;
    for (int r = tid; r < M_; r += 256) {
        float v = g_h0[(size_t)r * D_ + f];
        s += v; s2 += v * v;
    }
#pragma unroll
    for (int off = 16; off > 0; off >>= 1) {
        s  += __shfl_down_sync(0xffffffffu, s,  off);
        s2 += __shfl_down_sync(0xffffffffu, s2, off);
    }
    __shared__ float ws[8], ws2[8];
    if ((tid & 31) == 0) { ws[tid >> 5] = s; ws2[tid >> 5] = s2; }
    __syncthreads();
    if (tid == 0) {
        float S = 0.f, S2 = 0.f;
#pragma unroll
        for (int i = 0; i < 8; i++) { S += ws[i]; S2 += ws2[i]; }
        float mu  = S / (float)M_;
        float var = S2 / (float)M_ - mu * mu;
        g_mu[f]   = mu;
        g_rstd[f] = rsqrtf(var + EPS_);
    }
}

// =================================================================
// Kernel 3: BN affine + ReLU*mask + adds -> d_out
// =================================================================
__global__ __launch_bounds__(256) void apply_k(const float* __restrict__ gamma,
                                               const float* __restrict__ beta,
                                               const float* __restrict__ mask,
                                               const float* __restrict__ residual,
                                               const float* __restrict__ attention,
                                               const float* __restrict__ positional,
                                               float* __restrict__ out)
{
    const int n4 = (M_ * D_) / 4;
    for (int i = blockIdx.x * blockDim.x + threadIdx.x; i < n4;
         i += gridDim.x * blockDim.x) {
        const int f4 = i & (D_ / 4 - 1);
        float4 hv = ((const float4*)g_h0)[i];
        float4 g  = ((const float4*)gamma)[f4];
        float4 bt = ((const float4*)beta)[f4];
        float4 mu = ((const float4*)g_mu)[f4];
        float4 rs = ((const float4*)g_rstd)[f4];
        float4 mk = ((const float4*)mask)[i];
        float4 rd = ((const float4*)residual)[i];
        float4 at = ((const float4*)attention)[i];
        float4 ps = ((const float4*)positional)[i];
        float4 y;
        y.x = fmaxf(g.x * (hv.x - mu.x) * rs.x + bt.x, 0.f) * mk.x + rd.x + at.x + ps.x;
        y.y = fmaxf(g.y * (hv.y - mu.y) * rs.y + bt.y, 0.f) * mk.y + rd.y + at.y + ps.y;
        y.z = fmaxf(g.z * (hv.z - mu.z) * rs.z + bt.z, 0.f) * mk.z + rd.z + at.z + ps.z;
        y.w = fmaxf(g.w * (hv.w - mu.w) * rs.w + bt.w, 0.f) * mk.w + rd.w + at.w + ps.w;
        ((float4*)out)[i] = y;
    }
}

// =================================================================
// helpers (baseline PTX only: mma.sync + ldmatrix, sm_80+)
// =================================================================
__device__ __forceinline__ uint32_t u32s(const void* p) {
    uint32_t a;
    asm("{ .reg .u64 t; cvta.to.shared.u64 t, %1; cvt.u32.u64 %0, t; }"
        : "=r"(a) : "l"(p));
    return a;
}
__device__ __forceinline__ float bff(float x) {
    unsigned short hsh;
    asm("cvt.rn.bf16.f32 %0, %1;" : "=h"(hsh) : "f"(x));
    return __uint_as_float(((uint32_t)hsh) << 16);
}
__device__ __forceinline__ uint32_t bf2(float a, float b) {
    uint32_t r;
    asm("cvt.rn.bf16x2.f32 %0, %1, %2;" : "=r"(r) : "f"(b), "f"(a));
    return r;
}
__device__ __forceinline__ void mma16816(float* d, const uint32_t* a,
                                         uint32_t b0, uint32_t b1) {
    asm volatile("mma.sync.aligned.m16n8k16.row.col.f32.bf16.bf16.f32 "
                 "{%0,%1,%2,%3}, {%4,%5,%6,%7}, {%8,%9}, {%0,%1,%2,%3};"
                 : "+f"(d[0]), "+f"(d[1]), "+f"(d[2]), "+f"(d[3])
                 : "r"(a[0]), "r"(a[1]), "r"(a[2]), "r"(a[3]),
                   "r"(b0), "r"(b1));
}
__device__ __forceinline__ void ldm4(uint32_t* r, uint32_t addr) {
    asm volatile("ldmatrix.sync.aligned.m8n8.x4.shared.b16 {%0,%1,%2,%3}, [%4];"
                 : "=r"(r[0]), "=r"(r[1]), "=r"(r[2]), "=r"(r[3]) : "r"(addr));
}
__device__ __forceinline__ void ldm4t(uint32_t* r, uint32_t addr) {
    asm volatile("ldmatrix.sync.aligned.m8n8.x4.trans.shared.b16 {%0,%1,%2,%3}, [%4];"
                 : "=r"(r[0]), "=r"(r[1]), "=r"(r[2]), "=r"(r[3]) : "r"(addr));
}
#define SWZ(o) ((o) ^ (((o) >> 3) & 0x70))

// =================================================================
// Kernel 4 (x6): flash attention on HMMA, 2 m16 tiles per warp.
// Block = 128 query rows x 1 head; warp owns 32 rows (two m16 tiles
// sharing every K/V B-fragment -> per-row ldmatrix traffic halves vs
// the 16-row version; two independent MMA streams per warp).
// Split-bf16 (hi/lo, 3 products) for fp32-grade accuracy.
// Fixed-m0 softmax per row (chunk-0 max); O in fp32 fragments.
// =================================================================
#define QROWS 128

__global__ __launch_bounds__(128, 2) void attn_mma(float* __restrict__ h,
                                                   const float* __restrict__ qb,
                                                   const float* __restrict__ kb,
                                                   const float* __restrict__ vb)
{
    __shared__ __align__(1024) unsigned char sKhi[64 * 128];
    __shared__ __align__(1024) unsigned char sKlo[64 * 128];
    __shared__ __align__(1024) unsigned char sVhi[64 * 128];
    __shared__ __align__(1024) unsigned char sVlo[64 * 128];

    const int tid  = threadIdx.x;
    const int lane = tid & 31;
    const int warp = tid >> 5;
    const int hh   = blockIdx.y;
    const int b    = blockIdx.z;
    const int r0   = blockIdx.x * QROWS;

    const size_t headoff = ((size_t)b * S_) * D_ + hh * DH_;
    const int    cb      = (lane & 3) * 2;
    size_t rowoff[2];
    rowoff[0] = headoff + (size_t)(r0 + warp * 32 + (lane >> 2)) * D_;
    rowoff[1] = rowoff[0] + 16 * (size_t)D_;

    // ---- Q fragments (built once): 2 m-tiles ----
    uint32_t QH[2][4][4], QL[2][4][4];
#pragma unroll
    for (int mt = 0; mt < 2; mt++) {
        const float* h0 = h + rowoff[mt];
        const float* q0 = qb + rowoff[mt];
        const float* h1 = h0 + 8 * (size_t)D_;
        const float* q1 = q0 + 8 * (size_t)D_;
#pragma unroll
        for (int s = 0; s < 4; s++) {
            int c0 = s * 16 + cb, c1 = c0 + 8;
            float2 xa = *(const float2*)(h0 + c0), ya = *(const float2*)(q0 + c0);
            float2 xb = *(const float2*)(h1 + c0), yb = *(const float2*)(q1 + c0);
            float2 xc = *(const float2*)(h0 + c1), yc = *(const float2*)(q0 + c1);
            float2 xd = *(const float2*)(h1 + c1), yd = *(const float2*)(q1 + c1);
            float a0 = xa.x + ya.x, a1 = xa.y + ya.y;
            float b0 = xb.x + yb.x, b1 = xb.y + yb.y;
            float c0f = xc.x + yc.x, c1f = xc.y + yc.y;
            float d0 = xd.x + yd.x, d1 = xd.y + yd.y;
            QH[mt][s][0] = bf2(a0, a1);   QL[mt][s][0] = bf2(a0 - bff(a0), a1 - bff(a1));
            QH[mt][s][1] = bf2(b0, b1);   QL[mt][s][1] = bf2(b0 - bff(b0), b1 - bff(b1));
            QH[mt][s][2] = bf2(c0f, c1f); QL[mt][s][2] = bf2(c0f - bff(c0f), c1f - bff(c1f));
            QH[mt][s][3] = bf2(d0, d1);   QL[mt][s][3] = bf2(d0 - bff(d0), d1 - bff(d1));
        }
    }

    float O[2][8][4];
#pragma unroll
    for (int mt = 0; mt < 2; mt++)
#pragma unroll
        for (int t = 0; t < 8; t++)
#pragma unroll
            for (int j = 0; j < 4; j++) O[mt][t][j] = 0.f;
    float l0[2] = {0.f, 0.f}, l1[2] = {0.f, 0.f};
    float m0a[2] = {0.f, 0.f}, m0b[2] = {0.f, 0.f};

    const uint32_t bKhi = u32s(sKhi), bKlo = u32s(sKlo);
    const uint32_t bVhi = u32s(sVhi), bVlo = u32s(sVlo);
    const int lkey = tid >> 1, lhf = tid & 1;

    for (int ch = 0; ch < 16; ch++) {
        __syncthreads();
        // ---- K,V chunk -> smem (bf16 hi/lo, SW128) ----
        {
            const float4* gK = (const float4*)(kb + headoff + (size_t)(ch * 64 + lkey) * D_ + lhf * 32);
            const float4* gV = (const float4*)(vb + headoff + (size_t)(ch * 64 + lkey) * D_ + lhf * 32);
            uint32_t base = lkey * 128 + lhf * 64;
#pragma unroll
            for (int u = 0; u < 4; u++) {
                uint32_t off = SWZ(base + u * 16);
                float4 f0 = gK[u * 2], f1 = gK[u * 2 + 1];
                uint4 HI, LO;
                HI.x = bf2(f0.x, f0.y); HI.y = bf2(f0.z, f0.w);
                HI.z = bf2(f1.x, f1.y); HI.w = bf2(f1.z, f1.w);
                LO.x = bf2(f0.x - bff(f0.x), f0.y - bff(f0.y));
                LO.y = bf2(f0.z - bff(f0.z), f0.w - bff(f0.w));
                LO.z = bf2(f1.x - bff(f1.x), f1.y - bff(f1.y));
                LO.w = bf2(f1.z - bff(f1.z), f1.w - bff(f1.w));
                *(uint4*)(sKhi + off) = HI; *(uint4*)(sKlo + off) = LO;
                f0 = gV[u * 2]; f1 = gV[u * 2 + 1];
                HI.x = bf2(f0.x, f0.y); HI.y = bf2(f0.z, f0.w);
                HI.z = bf2(f1.x, f1.y); HI.w = bf2(f1.z, f1.w);
                LO.x = bf2(f0.x - bff(f0.x), f0.y - bff(f0.y));
                LO.y = bf2(f0.z - bff(f0.z), f0.w - bff(f0.w));
                LO.z = bf2(f1.x - bff(f1.x), f1.y - bff(f1.y));
                LO.w = bf2(f1.z - bff(f1.z), f1.w - bff(f1.w));
                *(uint4*)(sVhi + off) = HI; *(uint4*)(sVlo + off) = LO;
            }
        }
        __syncthreads();

        // ---- S = Q * K^T : each K fragment feeds BOTH m-tiles ----
        float Sacc[2][8][4];
#pragma unroll
        for (int mt = 0; mt < 2; mt++)
#pragma unroll
            for (int t = 0; t < 8; t++)
#pragma unroll
                for (int j = 0; j < 4; j++) Sacc[mt][t][j] = 0.f;

#pragma unroll
        for (int s = 0; s < 4; s++) {
#pragma unroll
            for (int tp = 0; tp < 4; tp++) {
                int m = lane >> 3;
                uint32_t key  = tp * 16 + (m >> 1) * 8 + (lane & 7);
                uint32_t byte = key * 128 + s * 32 + (m & 1) * 16;
                uint32_t kh[4], kl[4];
                ldm4(kh, bKhi + SWZ(byte));
                ldm4(kl, bKlo + SWZ(byte));
#pragma unroll
                for (int tt = 0; tt < 2; tt++) {
                    int t = 2 * tp + tt;
                    uint32_t b0h = kh[tt * 2], b1h = kh[tt * 2 + 1];
                    uint32_t b0l = kl[tt * 2], b1l = kl[tt * 2 + 1];
#pragma unroll
                    for (int mt = 0; mt < 2; mt++) {
                        mma16816(Sacc[mt][t], QH[mt][s], b0h, b1h);
                        mma16816(Sacc[mt][t], QH[mt][s], b0l, b1l);
                        mma16816(Sacc[mt][t], QL[mt][s], b0h, b1h);
                    }
                }
            }
        }

        if (ch == 0) {
#pragma unroll
            for (int mt = 0; mt < 2; mt++) {
                float ma = -1e30f, mb = -1e30f;
#pragma unroll
                for (int t = 0; t < 8; t++) {
                    ma = fmaxf(ma, fmaxf(Sacc[mt][t][0], Sacc[mt][t][1]));
                    mb = fmaxf(mb, fmaxf(Sacc[mt][t][2], Sacc[mt][t][3]));
                }
                ma = fmaxf(ma, __shfl_xor_sync(0xffffffffu, ma, 1));
                ma = fmaxf(ma, __shfl_xor_sync(0xffffffffu, ma, 2));
                mb = fmaxf(mb, __shfl_xor_sync(0xffffffffu, mb, 1));
                mb = fmaxf(mb, __shfl_xor_sync(0xffffffffu, mb, 2));
                m0a[mt] = ma * 0.125f;
                m0b[mt] = mb * 0.125f;
            }
        }

        // ---- O += P * V : each V fragment feeds BOTH m-tiles ----
#pragma unroll
        for (int s = 0; s < 4; s++) {
            uint32_t PHI[2][4], PLO[2][4];
#pragma unroll
            for (int mt = 0; mt < 2; mt++) {
                float p00 = __expf(Sacc[mt][2 * s][0] * 0.125f - m0a[mt]);
                float p01 = __expf(Sacc[mt][2 * s][1] * 0.125f - m0a[mt]);
                float p02 = __expf(Sacc[mt][2 * s][2] * 0.125f - m0b[mt]);
                float p03 = __expf(Sacc[mt][2 * s][3] * 0.125f - m0b[mt]);
                float p10 = __expf(Sacc[mt][2 * s + 1][0] * 0.125f - m0a[mt]);
                float p11 = __expf(Sacc[mt][2 * s + 1][1] * 0.125f - m0a[mt]);
                float p12 = __expf(Sacc[mt][2 * s + 1][2] * 0.125f - m0b[mt]);
                float p13 = __expf(Sacc[mt][2 * s + 1][3] * 0.125f - m0b[mt]);
                l0[mt] += p00 + p01 + p10 + p11;
                l1[mt] += p02 + p03 + p12 + p13;
                PHI[mt][0] = bf2(p00, p01); PLO[mt][0] = bf2(p00 - bff(p00), p01 - bff(p01));
                PHI[mt][1] = bf2(p02, p03); PLO[mt][1] = bf2(p02 - bff(p02), p03 - bff(p03));
                PHI[mt][2] = bf2(p10, p11); PLO[mt][2] = bf2(p10 - bff(p10), p11 - bff(p11));
                PHI[mt][3] = bf2(p12, p13); PLO[mt][3] = bf2(p12 - bff(p12), p13 - bff(p13));
            }
#pragma unroll
            for (int tp = 0; tp < 4; tp++) {
                int m = lane >> 3;
                uint32_t key  = s * 16 + (m & 1) * 8 + (lane & 7);
                uint32_t byte = key * 128 + tp * 32 + (m >> 1) * 16;
                uint32_t vh[4], vl[4];
                ldm4t(vh, bVhi + SWZ(byte));
                ldm4t(vl, bVlo + SWZ(byte));
#pragma unroll
                for (int tt = 0; tt < 2; tt++) {
                    int t = 2 * tp + tt;
                    uint32_t b0h = vh[tt * 2], b1h = vh[tt * 2 + 1];
                    uint32_t b0l = vl[tt * 2], b1l = vl[tt * 2 + 1];
#pragma unroll
                    for (int mt = 0; mt < 2; mt++) {
                        mma16816(O[mt][t], PHI[mt], b0h, b1h);
                        mma16816(O[mt][t], PHI[mt], b0l, b1l);
                        mma16816(O[mt][t], PLO[mt], b0h, b1h);
                    }
                }
            }
        }
    }

    // ---- epilogue: h[row] += O/l, both m-tiles ----
#pragma unroll
    for (int mt = 0; mt < 2; mt++) {
        float la = l0[mt], lb = l1[mt];
        la += __shfl_xor_sync(0xffffffffu, la, 1);
        la += __shfl_xor_sync(0xffffffffu, la, 2);
        lb += __shfl_xor_sync(0xffffffffu, lb, 1);
        lb += __shfl_xor_sync(0xffffffffu, lb, 2);
        const float inv0 = 1.f / la, inv1 = 1.f / lb;
        float* ho0 = h + rowoff[mt];
        float* ho1 = ho0 + 8 * (size_t)D_;
#pragma unroll
        for (int t = 0; t < 8; t++) {
            int c = t * 8 + cb;
            float2 v0 = *(float2*)(ho0 + c);
            v0.x += O[mt][t][0] * inv0; v0.y += O[mt][t][1] * inv0;
            *(float2*)(ho0 + c) = v0;
            float2 v1 = *(float2*)(ho1 + c);
            v1.x += O[mt][t][2] * inv1; v1.y += O[mt][t][3] * inv1;
            *(float2*)(ho1 + c) = v1;
        }
    }
}

// =================================================================
// launch
// =================================================================
extern "C" void kernel_launch(void* const* d_in, const int* in_sizes, int n_in,
                              void* d_out, int out_size)
{
    const float* x          = (const float*)d_in[0];
    const float* W          = (const float*)d_in[1];
    const float* scale      = (const float*)d_in[2];
    const float* gamma      = (const float*)d_in[3];
    const float* beta       = (const float*)d_in[4];
    const float* mask       = (const float*)d_in[5];
    const float* residual   = (const float*)d_in[6];
    const float* attention  = (const float*)d_in[7];
    const float* positional = (const float*)d_in[8];
    float* out = (float*)d_out;

    dim3 gg(D_ / BN, M_ / BM);
    gemm_k<<<gg, 256>>>(x, W, scale);

    stats_k<<<D_, 256>>>();

    apply_k<<<2048, 256>>>(gamma, beta, mask, residual, attention, positional, out);

    dim3 fg(S_ / QROWS, H_, B_);            // (8, 16, 4) = 512 blocks
    for (int t = 0; t < 6; t++) {
        attn_mma<<<fg, 128>>>(out,
                              (const float*)d_in[9  + 3 * t],
                              (const float*)d_in[10 + 3 * t],
                              (const float*)d_in[11 + 3 * t]);
    }
}